// round 7
// baseline (speedup 1.0000x reference)
#include <cuda_runtime.h>
#include <cuda_fp16.h>

// ---------------------------------------------------------------------------
// GATConv fused pipeline, round 3:
//   - tf32 tensor-core GEMM (mma.sync.m16n8k4), fused attn-coeff epilogue,
//     h stored as fp16 (77 MB -> L2-resident for the gather)
//   - CSR build (hist/scan/scatter)
//   - fused per-dst softmax + fp16 gather + head-mean + residual relu
// Shapes: N=50000, C=64, H=12, E=400000 (+N self loops)
// ---------------------------------------------------------------------------

namespace {
constexpr int CD = 64;
constexpr int HN = 12;
constexpr int HC = 768;
constexpr int N_CAP = 50176;
constexpr int E_CAP = 460800;
constexpr int SCAN_B = 1024;
constexpr int CHUNK = 96;
}

__device__ __half2 g_h [(size_t)N_CAP * HC / 2];
__device__ float g_asrc [N_CAP * HN];
__device__ float g_adst [N_CAP * HN];
__device__ int   g_deg  [N_CAP];
__device__ int   g_off  [N_CAP];
__device__ int   g_pos  [N_CAP];
__device__ int   g_bsum [128];
__device__ int   g_csr  [E_CAP];

__device__ __forceinline__ unsigned f2tf32(float f) {
    unsigned r;
    asm("cvt.rna.tf32.f32 %0, %1;" : "=r"(r) : "f"(f));
    return r;
}
__device__ __forceinline__ float tf32f(float f) {
    return __uint_as_float(f2tf32(f));
}

__device__ __forceinline__ void mma_tf32(float d[4], unsigned a0, unsigned a1,
                                         unsigned b0) {
    asm volatile(
        "mma.sync.aligned.m16n8k4.row.col.f32.tf32.tf32.f32 "
        "{%0,%1,%2,%3},{%4,%5},{%6},{%0,%1,%2,%3};"
        : "+f"(d[0]), "+f"(d[1]), "+f"(d[2]), "+f"(d[3])
        : "r"(a0), "r"(a1), "r"(b0));
}

// ---------------------------------------------------------------------------
__global__ void k_zero(int N) {
    int i = blockIdx.x * blockDim.x + threadIdx.x;
    if (i < N) g_deg[i] = 0;
}

// ---------------------------------------------------------------------------
// GEMM: 64 rows x 64 cols (one head) per block, 256 threads (8 warps, 2x4),
// warp tile 32x16, tf32 mma m16n8k4, K=64 resident. Epilogue: fp16 h store +
// fused a_src/a_dst dot for this head.
__global__ void __launch_bounds__(256) k_gemm(
    const float* __restrict__ x, const float* __restrict__ Wm,
    const float* __restrict__ att_src, const float* __restrict__ att_dst,
    int N) {
    __shared__ float xs[64][68];   // tf32-rounded A tile (reused as D stage)
    __shared__ float ws[64][68];   // tf32-rounded B tile
    int t = threadIdx.x;
    int brow = blockIdx.x * 64;
    int head = blockIdx.y;
    int bcol = head * 64;

    // fill A (64x64) and B (64x64), tf32-rounding each element
#pragma unroll
    for (int i = 0; i < 4; i++) {
        int v = i * 256 + t;          // float4 id in 64x16
        int r = v >> 4, k4 = v & 15;
        int gr = brow + r;
        float4 val = (gr < N) ? __ldg((const float4*)x + (size_t)gr * 16 + k4)
                              : make_float4(0.f, 0.f, 0.f, 0.f);
        val.x = tf32f(val.x); val.y = tf32f(val.y);
        val.z = tf32f(val.z); val.w = tf32f(val.w);
        *(float4*)&xs[r][k4 * 4] = val;
        int k = v >> 4, c4 = v & 15;
        float4 wv = __ldg((const float4*)Wm + (size_t)k * (HC / 4) + (bcol >> 2) + c4);
        wv.x = tf32f(wv.x); wv.y = tf32f(wv.y);
        wv.z = tf32f(wv.z); wv.w = tf32f(wv.w);
        *(float4*)&ws[k][c4 * 4] = wv;
    }
    __syncthreads();

    int w = t >> 5;
    int wm = w >> 2;          // 0..1  (32 rows)
    int wn = w & 3;           // 0..3  (16 cols)
    int lane = t & 31;
    int gp = lane >> 2, tc = lane & 3;

    float d[2][2][4] = {};    // [mt][nt][frag]
#pragma unroll
    for (int ks = 0; ks < 16; ks++) {
        unsigned a[2][2], b[2];
#pragma unroll
        for (int mt = 0; mt < 2; mt++) {
            int r = wm * 32 + mt * 16 + gp;
            a[mt][0] = __float_as_uint(xs[r][ks * 4 + tc]);
            a[mt][1] = __float_as_uint(xs[r + 8][ks * 4 + tc]);
        }
#pragma unroll
        for (int nt = 0; nt < 2; nt++)
            b[nt] = __float_as_uint(ws[ks * 4 + tc][wn * 16 + nt * 8 + gp]);
#pragma unroll
        for (int mt = 0; mt < 2; mt++)
#pragma unroll
            for (int nt = 0; nt < 2; nt++)
                mma_tf32(d[mt][nt], a[mt][0], a[mt][1], b[nt]);
    }
    __syncthreads();

    // stage D into xs (alias)
#pragma unroll
    for (int mt = 0; mt < 2; mt++)
#pragma unroll
        for (int nt = 0; nt < 2; nt++) {
            int r = wm * 32 + mt * 16 + gp;
            int c = wn * 16 + nt * 8 + 2 * tc;
            xs[r][c]     = d[mt][nt][0];
            xs[r][c + 1] = d[mt][nt][1];
            xs[r + 8][c]     = d[mt][nt][2];
            xs[r + 8][c + 1] = d[mt][nt][3];
        }
    __syncthreads();

    // output: 4 threads per row, 16 cols each: fp16 store + attn partial dots
    int r = t >> 2, q = t & 3, c0 = q * 16;
    int gr = brow + r;
    float ps = 0.f, pd = 0.f;
    __align__(16) __half2 hbuf[8];
#pragma unroll
    for (int j = 0; j < 4; j++) {
        float4 f = *(const float4*)&xs[r][c0 + j * 4];
        float4 as = __ldg((const float4*)att_src + head * 16 + (c0 >> 2) + j);
        float4 ad = __ldg((const float4*)att_dst + head * 16 + (c0 >> 2) + j);
        ps += f.x * as.x + f.y * as.y + f.z * as.z + f.w * as.w;
        pd += f.x * ad.x + f.y * ad.y + f.z * ad.z + f.w * ad.w;
        hbuf[j * 2]     = __floats2half2_rn(f.x, f.y);
        hbuf[j * 2 + 1] = __floats2half2_rn(f.z, f.w);
    }
    ps += __shfl_xor_sync(0xffffffffu, ps, 1);
    ps += __shfl_xor_sync(0xffffffffu, ps, 2);
    pd += __shfl_xor_sync(0xffffffffu, pd, 1);
    pd += __shfl_xor_sync(0xffffffffu, pd, 2);
    if (gr < N) {
        uint4* dst = (uint4*)&g_h[(size_t)gr * (HC / 2) + (head * CD + c0) / 2];
        dst[0] = ((uint4*)hbuf)[0];
        dst[1] = ((uint4*)hbuf)[1];
        if (q == 0) {
            g_asrc[gr * HN + head] = ps;
            g_adst[gr * HN + head] = pd;
        }
    }
}

// ---------------------------------------------------------------------------
__global__ void k_hist(const int* __restrict__ ei, int E, int Etot) {
    int e = blockIdx.x * blockDim.x + threadIdx.x;
    if (e >= Etot) return;
    int d = (e < E) ? ei[E + e] : (e - E);
    atomicAdd(&g_deg[d], 1);
}

__global__ void k_scan1(int N) {
    __shared__ int sm[SCAN_B];
    int i = blockIdx.x * SCAN_B + threadIdx.x;
    int v = (i < N) ? g_deg[i] : 0;
    sm[threadIdx.x] = v;
    __syncthreads();
#pragma unroll
    for (int o = 1; o < SCAN_B; o <<= 1) {
        int tv = (threadIdx.x >= o) ? sm[threadIdx.x - o] : 0;
        __syncthreads();
        sm[threadIdx.x] += tv;
        __syncthreads();
    }
    if (i < N) g_off[i] = sm[threadIdx.x] - v;
    if (threadIdx.x == SCAN_B - 1) g_bsum[blockIdx.x] = sm[SCAN_B - 1];
}

__global__ void k_scan2(int B) {
    __shared__ int sm[128];
    int tid = threadIdx.x;
    int v = (tid < B) ? g_bsum[tid] : 0;
    sm[tid] = v;
    __syncthreads();
#pragma unroll
    for (int o = 1; o < 128; o <<= 1) {
        int tv = (tid >= o) ? sm[tid - o] : 0;
        __syncthreads();
        sm[tid] += tv;
        __syncthreads();
    }
    if (tid < B) g_bsum[tid] = sm[tid] - v;
}

__global__ void k_scan3(int N) {
    int i = blockIdx.x * SCAN_B + threadIdx.x;
    if (i < N) {
        int o = g_off[i] + g_bsum[blockIdx.x];
        g_off[i] = o;
        g_pos[i] = o;
    }
}

__global__ void k_scatter(const int* __restrict__ ei, int E, int Etot) {
    int e = blockIdx.x * blockDim.x + threadIdx.x;
    if (e >= Etot) return;
    int s, d;
    if (e < E) { s = ei[e]; d = ei[E + e]; }
    else       { s = d = e - E; }
    int p = atomicAdd(&g_pos[d], 1);
    g_csr[p] = s;
}

// ---------------------------------------------------------------------------
// Fused per-dst aggregation. Block = 192 threads = one dst node.
__global__ void __launch_bounds__(192) k_agg(
    const float* __restrict__ x, const float* __restrict__ bias,
    float* __restrict__ y, int N) {
    __shared__ float s_m[HN], s_s[HN], s_ad[HN];
    __shared__ float s_w[CHUNK][HN];
    __shared__ int   s_src[CHUNK];
    __shared__ float4 s_red[192];

    int i = blockIdx.x;
    int tid = threadIdx.x;
    int off = g_off[i];
    int deg = g_deg[i];
    int h = tid >> 4, c4 = tid & 15;
    float4 acc = make_float4(0.f, 0.f, 0.f, 0.f);

    if (deg <= CHUNK) {
        // fast path: whole neighborhood resident in smem
        for (int e = tid; e < deg; e += 192) s_src[e] = g_csr[off + e];
        __syncthreads();
        if (tid < HN) {
            float ad = g_adst[i * HN + tid];
            float mx = -3.4e38f;
            for (int e = 0; e < deg; e++) {
                float v = g_asrc[s_src[e] * HN + tid] + ad;
                v = (v > 0.f) ? v : 0.2f * v;
                s_w[e][tid] = v;
                mx = fmaxf(mx, v);
            }
            float sum = 0.f;
            for (int e = 0; e < deg; e++) {
                float w = expf(s_w[e][tid] - mx);
                s_w[e][tid] = w;
                sum += w;
            }
            s_s[tid] = sum;
        }
        __syncthreads();
        for (int e = 0; e < deg; e++) {
            int src = s_src[e];
            float w = s_w[e][h];
            uint2 pv = *(const uint2*)&g_h[(size_t)src * (HC / 2) + h * (CD / 2) + c4 * 2];
            float2 f0 = __half22float2(*(__half2*)&pv.x);
            float2 f1 = __half22float2(*(__half2*)&pv.y);
            acc.x += w * f0.x; acc.y += w * f0.y;
            acc.z += w * f1.x; acc.w += w * f1.y;
        }
    } else {
        // generic chunked path
        if (tid < HN) {
            float ad = g_adst[i * HN + tid];
            s_ad[tid] = ad;
            float mx = -3.4e38f;
            for (int e = off; e < off + deg; e++) {
                float v = g_asrc[g_csr[e] * HN + tid] + ad;
                v = (v > 0.f) ? v : 0.2f * v;
                mx = fmaxf(mx, v);
            }
            s_m[tid] = mx;
            float sum = 0.f;
            for (int e = off; e < off + deg; e++) {
                float v = g_asrc[g_csr[e] * HN + tid] + ad;
                v = (v > 0.f) ? v : 0.2f * v;
                sum += expf(v - mx);
            }
            s_s[tid] = sum;
        }
        __syncthreads();
        for (int base = 0; base < deg; base += CHUNK) {
            int cnt = min(CHUNK, deg - base);
            for (int e = tid; e < cnt; e += 192) s_src[e] = g_csr[off + base + e];
            __syncthreads();
            if (tid < HN) {
                float ad = s_ad[tid], mx = s_m[tid];
                for (int e = 0; e < cnt; e++) {
                    float v = g_asrc[s_src[e] * HN + tid] + ad;
                    v = (v > 0.f) ? v : 0.2f * v;
                    s_w[e][tid] = expf(v - mx);
                }
            }
            __syncthreads();
            for (int e = 0; e < cnt; e++) {
                int src = s_src[e];
                float ww = s_w[e][h];
                uint2 pv = *(const uint2*)&g_h[(size_t)src * (HC / 2) + h * (CD / 2) + c4 * 2];
                float2 f0 = __half22float2(*(__half2*)&pv.x);
                float2 f1 = __half22float2(*(__half2*)&pv.y);
                acc.x += ww * f0.x; acc.y += ww * f0.y;
                acc.z += ww * f1.x; acc.w += ww * f1.y;
            }
            __syncthreads();
        }
    }

    float inv = 1.f / (s_s[h] + 1e-16f);
    acc.x *= inv; acc.y *= inv; acc.z *= inv; acc.w *= inv;
    s_red[tid] = acc;
    __syncthreads();

    if (tid < 16) {
        float4 sum = make_float4(0.f, 0.f, 0.f, 0.f);
#pragma unroll
        for (int hh = 0; hh < HN; hh++) {
            float4 v = s_red[hh * 16 + tid];
            sum.x += v.x; sum.y += v.y; sum.z += v.z; sum.w += v.w;
        }
        const float invH = 1.0f / (float)HN;
        float4 xv = __ldg((const float4*)x + (size_t)i * 16 + tid);
        float4 bv = __ldg((const float4*)bias + tid);
        float4 r;
        r.x = fmaxf(xv.x + sum.x * invH + bv.x, 0.f);
        r.y = fmaxf(xv.y + sum.y * invH + bv.y, 0.f);
        r.z = fmaxf(xv.z + sum.z * invH + bv.z, 0.f);
        r.w = fmaxf(xv.w + sum.w * invH + bv.w, 0.f);
        ((float4*)y)[(size_t)i * 16 + tid] = r;
    }
}

// ---------------------------------------------------------------------------
extern "C" void kernel_launch(void* const* d_in, const int* in_sizes, int n_in,
                              void* d_out, int out_size) {
    (void)n_in; (void)out_size;
    const float* x    = (const float*)d_in[0];
    const int*   ei   = (const int*)d_in[1];
    const float* Wm   = (const float*)d_in[2];
    const float* a_s  = (const float*)d_in[3];
    const float* a_d  = (const float*)d_in[4];
    const float* bias = (const float*)d_in[5];

    int N = in_sizes[0] / CD;
    int E = in_sizes[1] / 2;
    if (N > N_CAP) N = N_CAP;
    if (E + N > E_CAP) E = E_CAP - N;
    int Etot = E + N;
    int B = (N + SCAN_B - 1) / SCAN_B;

    k_zero<<<(N + 255) / 256, 256>>>(N);

    dim3 gg((N + 63) / 64, HN);
    k_gemm<<<gg, 256>>>(x, Wm, a_s, a_d, N);

    k_hist<<<(Etot + 255) / 256, 256>>>(ei, E, Etot);
    k_scan1<<<B, SCAN_B>>>(N);
    k_scan2<<<1, 128>>>(B);
    k_scan3<<<B, SCAN_B>>>(N);
    k_scatter<<<(Etot + 255) / 256, 256>>>(ei, E, Etot);

    k_agg<<<N, 192>>>(x, bias, (float*)d_out, N);
}

// round 9
// speedup vs baseline: 1.2194x; 1.2194x over previous
#include <cuda_runtime.h>
#include <cuda_fp16.h>

// ---------------------------------------------------------------------------
// GATConv fused pipeline (round-2 structure + fp16 h storage ONLY)
//   1. k_zero   : clear degree histogram
//   2. k_gemm   : h = x@W (fp32 FFMA) + fused a_src/a_dst epilogue; h -> fp16
//   3. k_hist/scan/scatter : CSR by dst
//   4. k_agg    : per-dst softmax + fp16 gather + head mean + residual relu
// Shapes: N=50000, C=64, H=12, E=400000 (+N self loops)
// ---------------------------------------------------------------------------

namespace {
constexpr int CD = 64;
constexpr int HN = 12;
constexpr int HC = 768;
constexpr int N_CAP = 50176;
constexpr int E_CAP = 460800;
constexpr int SCAN_B = 1024;
}

__device__ __half2 g_h [(size_t)N_CAP * HC / 2];   // fp16 projected features
__device__ float g_asrc [N_CAP * HN];
__device__ float g_adst [N_CAP * HN];
__device__ int   g_deg  [N_CAP];
__device__ int   g_off  [N_CAP];
__device__ int   g_pos  [N_CAP];
__device__ int   g_bsum [128];
__device__ int   g_csr  [E_CAP];

// ---------------------------------------------------------------------------
__global__ void k_zero(int N) {
    int i = blockIdx.x * blockDim.x + threadIdx.x;
    if (i < N) g_deg[i] = 0;
}

// ---------------------------------------------------------------------------
// GEMM h = x@W, block = 128 rows x 64 cols (one head), 256 threads,
// thread tile 8x4, full K=64 in smem. Epilogue: fp16 h store + fused attn dot.
__global__ void k_gemm(const float* __restrict__ x, const float* __restrict__ Wm,
                       const float* __restrict__ att_src,
                       const float* __restrict__ att_dst, int N) {
    __shared__ float xs[128][64];
    __shared__ float ws[64][64];
    int t = threadIdx.x;
    int brow = blockIdx.x * 128;
    int head = blockIdx.y;            // col block == head
    int bcol = head * 64;

#pragma unroll
    for (int i = 0; i < 8; i++) {
        int v = i * 256 + t;
        int r = v >> 4, k4 = v & 15;
        int gr = brow + r;
        float4 val = (gr < N) ? __ldg((const float4*)x + (size_t)gr * 16 + k4)
                              : make_float4(0.f, 0.f, 0.f, 0.f);
        *(float4*)&xs[r][k4 * 4] = val;
    }
#pragma unroll
    for (int i = 0; i < 4; i++) {
        int v = i * 256 + t;
        int k = v >> 4, c4 = v & 15;
        *(float4*)&ws[k][c4 * 4] =
            __ldg((const float4*)Wm + (size_t)k * (HC / 4) + (bcol >> 2) + c4);
    }
    __syncthreads();

    int ty = t >> 4, tx = t & 15;
    int r0 = ty * 8, c0 = tx * 4;
    float acc[8][4] = {};
#pragma unroll
    for (int k = 0; k < 64; k++) {
        float4 b = *(const float4*)&ws[k][c0];
#pragma unroll
        for (int i = 0; i < 8; i++) {
            float a = xs[r0 + i][k];
            acc[i][0] += a * b.x; acc[i][1] += a * b.y;
            acc[i][2] += a * b.z; acc[i][3] += a * b.w;
        }
    }

    // store h tile as fp16
#pragma unroll
    for (int i = 0; i < 8; i++) {
        int gr = brow + r0 + i;
        if (gr < N) {
            __align__(8) __half2 hb[2];
            hb[0] = __floats2half2_rn(acc[i][0], acc[i][1]);
            hb[1] = __floats2half2_rn(acc[i][2], acc[i][3]);
            *(uint2*)&g_h[(size_t)gr * (HC / 2) + (bcol + c0) / 2] =
                *(const uint2*)hb;
        }
    }

    // fused attention coefficients for this head (fp32 accumulators)
    float4 avs = __ldg((const float4*)att_src + head * 16 + tx);
    float4 avd = __ldg((const float4*)att_dst + head * 16 + tx);
#pragma unroll
    for (int i = 0; i < 8; i++) {
        float ps = acc[i][0] * avs.x + acc[i][1] * avs.y +
                   acc[i][2] * avs.z + acc[i][3] * avs.w;
        float pd = acc[i][0] * avd.x + acc[i][1] * avd.y +
                   acc[i][2] * avd.z + acc[i][3] * avd.w;
#pragma unroll
        for (int o = 8; o; o >>= 1) {
            ps += __shfl_xor_sync(0xffffffffu, ps, o);
            pd += __shfl_xor_sync(0xffffffffu, pd, o);
        }
        int gr = brow + r0 + i;
        if (tx == 0 && gr < N) {
            g_asrc[gr * HN + head] = ps;
            g_adst[gr * HN + head] = pd;
        }
    }
}

// ---------------------------------------------------------------------------
__global__ void k_hist(const int* __restrict__ ei, int E, int Etot) {
    int e = blockIdx.x * blockDim.x + threadIdx.x;
    if (e >= Etot) return;
    int d = (e < E) ? ei[E + e] : (e - E);
    atomicAdd(&g_deg[d], 1);
}

__global__ void k_scan1(int N) {
    __shared__ int sm[SCAN_B];
    int i = blockIdx.x * SCAN_B + threadIdx.x;
    int v = (i < N) ? g_deg[i] : 0;
    sm[threadIdx.x] = v;
    __syncthreads();
#pragma unroll
    for (int o = 1; o < SCAN_B; o <<= 1) {
        int tv = (threadIdx.x >= o) ? sm[threadIdx.x - o] : 0;
        __syncthreads();
        sm[threadIdx.x] += tv;
        __syncthreads();
    }
    if (i < N) g_off[i] = sm[threadIdx.x] - v;
    if (threadIdx.x == SCAN_B - 1) g_bsum[blockIdx.x] = sm[SCAN_B - 1];
}

__global__ void k_scan2(int B) {
    __shared__ int sm[128];
    int tid = threadIdx.x;
    int v = (tid < B) ? g_bsum[tid] : 0;
    sm[tid] = v;
    __syncthreads();
#pragma unroll
    for (int o = 1; o < 128; o <<= 1) {
        int tv = (tid >= o) ? sm[tid - o] : 0;
        __syncthreads();
        sm[tid] += tv;
        __syncthreads();
    }
    if (tid < B) g_bsum[tid] = sm[tid] - v;
}

__global__ void k_scan3(int N) {
    int i = blockIdx.x * SCAN_B + threadIdx.x;
    if (i < N) {
        int o = g_off[i] + g_bsum[blockIdx.x];
        g_off[i] = o;
        g_pos[i] = o;
    }
}

__global__ void k_scatter(const int* __restrict__ ei, int E, int Etot) {
    int e = blockIdx.x * blockDim.x + threadIdx.x;
    if (e >= Etot) return;
    int s, d;
    if (e < E) { s = ei[e]; d = ei[E + e]; }
    else       { s = d = e - E; }
    int p = atomicAdd(&g_pos[d], 1);
    g_csr[p] = s;
}

// ---------------------------------------------------------------------------
// Fused per-dst: softmax + weighted fp16 gather + head mean + residual relu.
// Block = 192 threads, one dst node.  (Identical structure to the 399us
// version; only the h loads are fp16 now.)
__global__ void __launch_bounds__(192) k_agg(
    const float* __restrict__ x, const float* __restrict__ bias,
    float* __restrict__ y, int N) {
    __shared__ float s_m[HN], s_s[HN], s_ad[HN];
    __shared__ float4 s_red[192];

    int i = blockIdx.x;
    int tid = threadIdx.x;
    int off = g_off[i];
    int deg = g_deg[i];

    if (tid < HN) {
        int h = tid;
        float ad = g_adst[i * HN + h];
        s_ad[h] = ad;
        float mx = -3.4e38f;
        for (int e = off; e < off + deg; e++) {
            float v = g_asrc[g_csr[e] * HN + h] + ad;
            v = (v > 0.f) ? v : 0.2f * v;
            mx = fmaxf(mx, v);
        }
        s_m[h] = mx;
        float sum = 0.f;
        for (int e = off; e < off + deg; e++) {
            float v = g_asrc[g_csr[e] * HN + h] + ad;
            v = (v > 0.f) ? v : 0.2f * v;
            sum += expf(v - mx);
        }
        s_s[h] = sum;
    }
    __syncthreads();

    int h = tid >> 4;          // head 0..11
    int c4 = tid & 15;         // float4-equivalent lane within head channels
    float ad = s_ad[h], mh = s_m[h];
    float4 acc = make_float4(0.f, 0.f, 0.f, 0.f);
    for (int e = off; e < off + deg; e++) {
        int src = g_csr[e];
        float v = g_asrc[src * HN + h] + ad;
        v = (v > 0.f) ? v : 0.2f * v;
        float w = expf(v - mh);
        uint2 pv = *(const uint2*)&g_h[(size_t)src * (HC / 2) + h * (CD / 2) + c4 * 2];
        float2 f0 = __half22float2(*reinterpret_cast<const __half2*>(&pv.x));
        float2 f1 = __half22float2(*reinterpret_cast<const __half2*>(&pv.y));
        acc.x += w * f0.x; acc.y += w * f0.y;
        acc.z += w * f1.x; acc.w += w * f1.y;
    }
    float inv = 1.f / (s_s[h] + 1e-16f);
    acc.x *= inv; acc.y *= inv; acc.z *= inv; acc.w *= inv;
    s_red[tid] = acc;
    __syncthreads();

    if (tid < 16) {
        float4 sum = make_float4(0.f, 0.f, 0.f, 0.f);
#pragma unroll
        for (int hh = 0; hh < HN; hh++) {
            float4 v = s_red[hh * 16 + tid];
            sum.x += v.x; sum.y += v.y; sum.z += v.z; sum.w += v.w;
        }
        const float invH = 1.0f / (float)HN;
        float4 xv = __ldg((const float4*)x + (size_t)i * 16 + tid);
        float4 bv = __ldg((const float4*)bias + tid);
        float4 r;
        r.x = fmaxf(xv.x + sum.x * invH + bv.x, 0.f);
        r.y = fmaxf(xv.y + sum.y * invH + bv.y, 0.f);
        r.z = fmaxf(xv.z + sum.z * invH + bv.z, 0.f);
        r.w = fmaxf(xv.w + sum.w * invH + bv.w, 0.f);
        ((float4*)y)[(size_t)i * 16 + tid] = r;
    }
}

// ---------------------------------------------------------------------------
extern "C" void kernel_launch(void* const* d_in, const int* in_sizes, int n_in,
                              void* d_out, int out_size) {
    (void)n_in; (void)out_size;
    const float* x    = (const float*)d_in[0];
    const int*   ei   = (const int*)d_in[1];
    const float* Wm   = (const float*)d_in[2];
    const float* a_s  = (const float*)d_in[3];
    const float* a_d  = (const float*)d_in[4];
    const float* bias = (const float*)d_in[5];

    int N = in_sizes[0] / CD;
    int E = in_sizes[1] / 2;
    if (N > N_CAP) N = N_CAP;
    if (E + N > E_CAP) E = E_CAP - N;
    int Etot = E + N;
    int B = (N + SCAN_B - 1) / SCAN_B;

    k_zero<<<(N + 255) / 256, 256>>>(N);

    dim3 gg((N + 127) / 128, HN);
    k_gemm<<<gg, 256>>>(x, Wm, a_s, a_d, N);

    k_hist<<<(Etot + 255) / 256, 256>>>(ei, E, Etot);
    k_scan1<<<B, SCAN_B>>>(N);
    k_scan2<<<1, 128>>>(B);
    k_scan3<<<B, SCAN_B>>>(N);
    k_scatter<<<(Etot + 255) / 256, 256>>>(ei, E, Etot);

    k_agg<<<N, 192>>>(x, bias, (float*)d_out, N);
}

// round 10
// speedup vs baseline: 1.3717x; 1.1249x over previous
#include <cuda_runtime.h>
#include <cuda_fp16.h>

// ---------------------------------------------------------------------------
// GATConv fused pipeline (round-9 structure; GEMM switched to fp16 HMMA)
//   1. k_zero   : clear degree histogram
//   2. k_gemm   : h = x@W (fp16 mma.m16n8k16, fp32 accum) + attn epilogue
//   3. k_hist/scan/scatter : CSR by dst
//   4. k_agg    : per-dst softmax + fp16 gather + head mean + residual relu
// Shapes: N=50000, C=64, H=12, E=400000 (+N self loops)
// ---------------------------------------------------------------------------

namespace {
constexpr int CD = 64;
constexpr int HN = 12;
constexpr int HC = 768;
constexpr int N_CAP = 50176;
constexpr int E_CAP = 460800;
constexpr int SCAN_B = 1024;
constexpr int XPAD = 72;          // smem row stride in halves (36 words)
}

__device__ __half2 g_h [(size_t)N_CAP * HC / 2];   // fp16 projected features
__device__ float g_asrc [N_CAP * HN];
__device__ float g_adst [N_CAP * HN];
__device__ int   g_deg  [N_CAP];
__device__ int   g_off  [N_CAP];
__device__ int   g_pos  [N_CAP];
__device__ int   g_bsum [128];
__device__ int   g_csr  [E_CAP];

__device__ __forceinline__ void mma_f16(float d[4], unsigned a0, unsigned a1,
                                        unsigned a2, unsigned a3,
                                        unsigned b0, unsigned b1) {
    asm volatile(
        "mma.sync.aligned.m16n8k16.row.col.f32.f16.f16.f32 "
        "{%0,%1,%2,%3},{%4,%5,%6,%7},{%8,%9},{%0,%1,%2,%3};"
        : "+f"(d[0]), "+f"(d[1]), "+f"(d[2]), "+f"(d[3])
        : "r"(a0), "r"(a1), "r"(a2), "r"(a3), "r"(b0), "r"(b1));
}

// ---------------------------------------------------------------------------
__global__ void k_zero(int N) {
    int i = blockIdx.x * blockDim.x + threadIdx.x;
    if (i < N) g_deg[i] = 0;
}

// ---------------------------------------------------------------------------
// GEMM h = x@W via fp16 HMMA. Block = 128 rows x 64 cols (one head),
// 256 threads = 8 warps (4m x 2n), warp tile 32x32, mma m16n8k16, K=64.
__global__ void __launch_bounds__(256) k_gemm(
    const float* __restrict__ x, const float* __restrict__ Wm,
    const float* __restrict__ att_src, const float* __restrict__ att_dst,
    int N) {
    __shared__ __half xs[128][XPAD];   // A tile (fp16), later reused for D
    __shared__ __half ws[64][XPAD];    // B tile TRANSPOSED: ws[n][k]
    int t = threadIdx.x;
    int brow = blockIdx.x * 128;
    int head = blockIdx.y;
    int bcol = head * 64;

    // fill A: x[128][64] -> fp16
#pragma unroll
    for (int i = 0; i < 8; i++) {
        int v = i * 256 + t;
        int r = v >> 4, k4 = v & 15;
        int gr = brow + r;
        float4 val = (gr < N) ? __ldg((const float4*)x + (size_t)gr * 16 + k4)
                              : make_float4(0.f, 0.f, 0.f, 0.f);
        __align__(8) __half2 hb[2];
        hb[0] = __floats2half2_rn(val.x, val.y);
        hb[1] = __floats2half2_rn(val.z, val.w);
        *(uint2*)&xs[r][k4 * 4] = *(const uint2*)hb;
    }
    // fill B transposed: W[k][bcol+n] -> ws[n][k] fp16
#pragma unroll
    for (int i = 0; i < 4; i++) {
        int v = i * 256 + t;
        int k = v >> 4, c4 = v & 15;
        float4 wv = __ldg((const float4*)Wm + (size_t)k * (HC / 4) + (bcol >> 2) + c4);
        ws[c4 * 4 + 0][k] = __float2half_rn(wv.x);
        ws[c4 * 4 + 1][k] = __float2half_rn(wv.y);
        ws[c4 * 4 + 2][k] = __float2half_rn(wv.z);
        ws[c4 * 4 + 3][k] = __float2half_rn(wv.w);
    }
    __syncthreads();

    int warp = t >> 5, lane = t & 31;
    int wm = warp >> 1;               // 0..3 : rows wm*32..+31
    int wn = warp & 1;                // 0..1 : cols wn*32..+31
    int gp = lane >> 2, ctid = lane & 3;

    float c[2][4][4] = {};            // [mt][nt][frag]
#pragma unroll
    for (int ks = 0; ks < 4; ks++) {
        int k0 = ks * 16;
        unsigned a[2][4], b[4][2];
#pragma unroll
        for (int mt = 0; mt < 2; mt++) {
            int r = wm * 32 + mt * 16 + gp;
            a[mt][0] = *(const unsigned*)&xs[r][k0 + ctid * 2];
            a[mt][1] = *(const unsigned*)&xs[r + 8][k0 + ctid * 2];
            a[mt][2] = *(const unsigned*)&xs[r][k0 + ctid * 2 + 8];
            a[mt][3] = *(const unsigned*)&xs[r + 8][k0 + ctid * 2 + 8];
        }
#pragma unroll
        for (int nt = 0; nt < 4; nt++) {
            int n = wn * 32 + nt * 8 + gp;
            b[nt][0] = *(const unsigned*)&ws[n][k0 + ctid * 2];
            b[nt][1] = *(const unsigned*)&ws[n][k0 + ctid * 2 + 8];
        }
#pragma unroll
        for (int mt = 0; mt < 2; mt++)
#pragma unroll
            for (int nt = 0; nt < 4; nt++)
                mma_f16(c[mt][nt], a[mt][0], a[mt][1], a[mt][2], a[mt][3],
                        b[nt][0], b[nt][1]);
    }
    __syncthreads();

    // stage D (as fp16) into xs
#pragma unroll
    for (int mt = 0; mt < 2; mt++)
#pragma unroll
        for (int nt = 0; nt < 4; nt++) {
            int r = wm * 32 + mt * 16 + gp;
            int col = wn * 32 + nt * 8 + ctid * 2;
            *(__half2*)&xs[r][col]     = __floats2half2_rn(c[mt][nt][0], c[mt][nt][1]);
            *(__half2*)&xs[r + 8][col] = __floats2half2_rn(c[mt][nt][2], c[mt][nt][3]);
        }
    __syncthreads();

    // epilogue: 2 threads per row, 32 halves each -> coalesced h store + attn dots
    {
        int r = t >> 1, half0 = (t & 1) * 32;
        int gr = brow + r;
        __align__(16) __half hbuf[32];
#pragma unroll
        for (int j = 0; j < 4; j++)
            ((uint4*)hbuf)[j] = *(const uint4*)&xs[r][half0 + j * 8];

        float ps = 0.f, pd = 0.f;
#pragma unroll
        for (int j = 0; j < 8; j++) {
            float4 as = __ldg((const float4*)att_src + head * 16 + (half0 >> 2) + j);
            float4 ad = __ldg((const float4*)att_dst + head * 16 + (half0 >> 2) + j);
            float f0 = __half2float(hbuf[j * 4 + 0]);
            float f1 = __half2float(hbuf[j * 4 + 1]);
            float f2 = __half2float(hbuf[j * 4 + 2]);
            float f3 = __half2float(hbuf[j * 4 + 3]);
            ps += f0 * as.x + f1 * as.y + f2 * as.z + f3 * as.w;
            pd += f0 * ad.x + f1 * ad.y + f2 * ad.z + f3 * ad.w;
        }
        ps += __shfl_xor_sync(0xffffffffu, ps, 1);
        pd += __shfl_xor_sync(0xffffffffu, pd, 1);

        if (gr < N) {
            uint4* dst = (uint4*)&g_h[((size_t)gr * HC + bcol + half0) / 2];
#pragma unroll
            for (int j = 0; j < 4; j++) dst[j] = ((const uint4*)hbuf)[j];
            if ((t & 1) == 0) {
                g_asrc[gr * HN + head] = ps;
                g_adst[gr * HN + head] = pd;
            }
        }
    }
}

// ---------------------------------------------------------------------------
__global__ void k_hist(const int* __restrict__ ei, int E, int Etot) {
    int e = blockIdx.x * blockDim.x + threadIdx.x;
    if (e >= Etot) return;
    int d = (e < E) ? ei[E + e] : (e - E);
    atomicAdd(&g_deg[d], 1);
}

__global__ void k_scan1(int N) {
    __shared__ int sm[SCAN_B];
    int i = blockIdx.x * SCAN_B + threadIdx.x;
    int v = (i < N) ? g_deg[i] : 0;
    sm[threadIdx.x] = v;
    __syncthreads();
#pragma unroll
    for (int o = 1; o < SCAN_B; o <<= 1) {
        int tv = (threadIdx.x >= o) ? sm[threadIdx.x - o] : 0;
        __syncthreads();
        sm[threadIdx.x] += tv;
        __syncthreads();
    }
    if (i < N) g_off[i] = sm[threadIdx.x] - v;
    if (threadIdx.x == SCAN_B - 1) g_bsum[blockIdx.x] = sm[SCAN_B - 1];
}

__global__ void k_scan2(int B) {
    __shared__ int sm[128];
    int tid = threadIdx.x;
    int v = (tid < B) ? g_bsum[tid] : 0;
    sm[tid] = v;
    __syncthreads();
#pragma unroll
    for (int o = 1; o < 128; o <<= 1) {
        int tv = (tid >= o) ? sm[tid - o] : 0;
        __syncthreads();
        sm[tid] += tv;
        __syncthreads();
    }
    if (tid < B) g_bsum[tid] = sm[tid] - v;
}

__global__ void k_scan3(int N) {
    int i = blockIdx.x * SCAN_B + threadIdx.x;
    if (i < N) {
        int o = g_off[i] + g_bsum[blockIdx.x];
        g_off[i] = o;
        g_pos[i] = o;
    }
}

__global__ void k_scatter(const int* __restrict__ ei, int E, int Etot) {
    int e = blockIdx.x * blockDim.x + threadIdx.x;
    if (e >= Etot) return;
    int s, d;
    if (e < E) { s = ei[e]; d = ei[E + e]; }
    else       { s = d = e - E; }
    int p = atomicAdd(&g_pos[d], 1);
    g_csr[p] = s;
}

// ---------------------------------------------------------------------------
// Fused per-dst: softmax + weighted fp16 gather + head mean + residual relu.
__global__ void __launch_bounds__(192) k_agg(
    const float* __restrict__ x, const float* __restrict__ bias,
    float* __restrict__ y, int N) {
    __shared__ float s_m[HN], s_s[HN], s_ad[HN];
    __shared__ float4 s_red[192];

    int i = blockIdx.x;
    int tid = threadIdx.x;
    int off = g_off[i];
    int deg = g_deg[i];

    if (tid < HN) {
        int h = tid;
        float ad = g_adst[i * HN + h];
        s_ad[h] = ad;
        float mx = -3.4e38f;
        for (int e = off; e < off + deg; e++) {
            float v = g_asrc[g_csr[e] * HN + h] + ad;
            v = (v > 0.f) ? v : 0.2f * v;
            mx = fmaxf(mx, v);
        }
        s_m[h] = mx;
        float sum = 0.f;
        for (int e = off; e < off + deg; e++) {
            float v = g_asrc[g_csr[e] * HN + h] + ad;
            v = (v > 0.f) ? v : 0.2f * v;
            sum += expf(v - mx);
        }
        s_s[h] = sum;
    }
    __syncthreads();

    int h = tid >> 4;
    int c4 = tid & 15;
    float ad = s_ad[h], mh = s_m[h];
    float4 acc = make_float4(0.f, 0.f, 0.f, 0.f);
    for (int e = off; e < off + deg; e++) {
        int src = g_csr[e];
        float v = g_asrc[src * HN + h] + ad;
        v = (v > 0.f) ? v : 0.2f * v;
        float w = expf(v - mh);
        uint2 pv = *(const uint2*)&g_h[(size_t)src * (HC / 2) + h * (CD / 2) + c4 * 2];
        float2 f0 = __half22float2(*reinterpret_cast<const __half2*>(&pv.x));
        float2 f1 = __half22float2(*reinterpret_cast<const __half2*>(&pv.y));
        acc.x += w * f0.x; acc.y += w * f0.y;
        acc.z += w * f1.x; acc.w += w * f1.y;
    }
    float inv = 1.f / (s_s[h] + 1e-16f);
    acc.x *= inv; acc.y *= inv; acc.z *= inv; acc.w *= inv;
    s_red[tid] = acc;
    __syncthreads();

    if (tid < 16) {
        float4 sum = make_float4(0.f, 0.f, 0.f, 0.f);
#pragma unroll
        for (int hh = 0; hh < HN; hh++) {
            float4 v = s_red[hh * 16 + tid];
            sum.x += v.x; sum.y += v.y; sum.z += v.z; sum.w += v.w;
        }
        const float invH = 1.0f / (float)HN;
        float4 xv = __ldg((const float4*)x + (size_t)i * 16 + tid);
        float4 bv = __ldg((const float4*)bias + tid);
        float4 r;
        r.x = fmaxf(xv.x + sum.x * invH + bv.x, 0.f);
        r.y = fmaxf(xv.y + sum.y * invH + bv.y, 0.f);
        r.z = fmaxf(xv.z + sum.z * invH + bv.z, 0.f);
        r.w = fmaxf(xv.w + sum.w * invH + bv.w, 0.f);
        ((float4*)y)[(size_t)i * 16 + tid] = r;
    }
}

// ---------------------------------------------------------------------------
extern "C" void kernel_launch(void* const* d_in, const int* in_sizes, int n_in,
                              void* d_out, int out_size) {
    (void)n_in; (void)out_size;
    const float* x    = (const float*)d_in[0];
    const int*   ei   = (const int*)d_in[1];
    const float* Wm   = (const float*)d_in[2];
    const float* a_s  = (const float*)d_in[3];
    const float* a_d  = (const float*)d_in[4];
    const float* bias = (const float*)d_in[5];

    int N = in_sizes[0] / CD;
    int E = in_sizes[1] / 2;
    if (N > N_CAP) N = N_CAP;
    if (E + N > E_CAP) E = E_CAP - N;
    int Etot = E + N;
    int B = (N + SCAN_B - 1) / SCAN_B;

    k_zero<<<(N + 255) / 256, 256>>>(N);

    dim3 gg((N + 127) / 128, HN);
    k_gemm<<<gg, 256>>>(x, Wm, a_s, a_d, N);

    k_hist<<<(Etot + 255) / 256, 256>>>(ei, E, Etot);
    k_scan1<<<B, SCAN_B>>>(N);
    k_scan2<<<1, 128>>>(B);
    k_scan3<<<B, SCAN_B>>>(N);
    k_scatter<<<(Etot + 255) / 256, 256>>>(ei, E, Etot);

    k_agg<<<N, 192>>>(x, bias, (float*)d_out, N);
}